// round 12
// baseline (speedup 1.0000x reference)
#include <cuda_runtime.h>
#include <cuda_fp16.h>
#include <math.h>
#include <stdint.h>

#define BB 2
#define SS 2048
#define DD 1024
#define HH 16
#define DHH 64
#define MM (BB * SS)
#define LD3 (3 * DD)

// ---------------- scratch ----------------
__device__ float g_attn[MM * DD];
__device__ float g_ln2f[MM * DD];
__device__ float g_res2[MM * DD];

__device__ __half g_ln1h[MM * DD];
__device__ __half g_ln2h[MM * DD];
__device__ __half g_ctxh[MM * DD];
__device__ __half g_f1h [MM * DD];
__device__ __half g_qkvh[MM * LD3];
__device__ __half g_wqh[LD3 * DD];
__device__ __half g_woh[DD * DD];
__device__ __half g_w1h[DD * DD];
__device__ __half g_w2h[DD * DD];

// ---------------- helpers ----------------
__device__ __forceinline__ uint32_t smem_u32(const void* p) {
    uint32_t a;
    asm("{ .reg .u64 t; cvta.to.shared.u64 t, %1; cvt.u32.u64 %0, t; }" : "=r"(a) : "l"(p));
    return a;
}
__device__ __forceinline__ void cpa16(uint32_t dst, const void* src) {
    asm volatile("cp.async.cg.shared.global [%0], [%1], 16;" :: "r"(dst), "l"(src) : "memory");
}
__device__ __forceinline__ void cpcommit() { asm volatile("cp.async.commit_group;" ::: "memory"); }
template <int N> __device__ __forceinline__ void cpwait() {
    asm volatile("cp.async.wait_group %0;" :: "n"(N) : "memory");
}
__device__ __forceinline__ void ldsm_x4(uint32_t* r, uint32_t a) {
    asm volatile("ldmatrix.sync.aligned.m8n8.x4.shared.b16 {%0,%1,%2,%3}, [%4];"
        : "=r"(r[0]), "=r"(r[1]), "=r"(r[2]), "=r"(r[3]) : "r"(a));
}
__device__ __forceinline__ void ldsm_x4t(uint32_t* r, uint32_t a) {
    asm volatile("ldmatrix.sync.aligned.m8n8.x4.trans.shared.b16 {%0,%1,%2,%3}, [%4];"
        : "=r"(r[0]), "=r"(r[1]), "=r"(r[2]), "=r"(r[3]) : "r"(a));
}
__device__ __forceinline__ void mma16816(float* d, const uint32_t* a, const uint32_t* b) {
    asm volatile("mma.sync.aligned.m16n8k16.row.col.f32.f16.f16.f32 "
        "{%0,%1,%2,%3},{%4,%5,%6,%7},{%8,%9},{%0,%1,%2,%3};"
        : "+f"(d[0]), "+f"(d[1]), "+f"(d[2]), "+f"(d[3])
        : "r"(a[0]), "r"(a[1]), "r"(a[2]), "r"(a[3]), "r"(b[0]), "r"(b[1]));
}
__device__ __forceinline__ uint32_t packh(float a, float b) {
    __half2 t = __floats2half2_rn(a, b);
    return *(uint32_t*)&t;
}

// ---------------- layernorm ----------------
__device__ __forceinline__ float block_sum_256(float v, float* red) {
    #pragma unroll
    for (int o = 16; o; o >>= 1) v += __shfl_xor_sync(0xffffffffu, v, o);
    int w = threadIdx.x >> 5;
    if ((threadIdx.x & 31) == 0) red[w] = v;
    __syncthreads();
    if (threadIdx.x < 8) {
        v = red[threadIdx.x];
        #pragma unroll
        for (int o = 4; o; o >>= 1) v += __shfl_xor_sync(0xffu, v, o);
        if (threadIdx.x == 0) red[0] = v;
    }
    __syncthreads();
    float r = red[0];
    __syncthreads();
    return r;
}

__global__ void layernorm_kernel(const float* __restrict__ x,
                                 const float* __restrict__ g,
                                 const float* __restrict__ b,
                                 float* __restrict__ outf,
                                 __half* __restrict__ outh) {
    __shared__ float red[32];
    int row = blockIdx.x;
    const float* xr = x + (size_t)row * DD;
    float v[4], s = 0.f;
    #pragma unroll
    for (int i = 0; i < 4; i++) { v[i] = xr[threadIdx.x + i * 256]; s += v[i]; }
    float mean = block_sum_256(s, red) * (1.0f / DD);
    float sq = 0.f;
    #pragma unroll
    for (int i = 0; i < 4; i++) { float d = v[i] - mean; sq += d * d; }
    float inv = rsqrtf(block_sum_256(sq, red) * (1.0f / DD) + 1e-5f);
    #pragma unroll
    for (int i = 0; i < 4; i++) {
        int c = threadIdx.x + i * 256;
        float y = (v[i] - mean) * inv * g[c] + b[c];
        size_t o = (size_t)row * DD + c;
        if (outf) outf[o] = y;
        if (outh) outh[o] = __float2half_rn(y);
    }
}

// ---------------- weight transposes -> [N,K] single fp16 ----------------
__global__ void transpose_qkv_kernel(const float* __restrict__ wq, const float* __restrict__ wk,
                                     const float* __restrict__ wv,
                                     __half* __restrict__ th) {
    __shared__ float t[32][33];
    int sel = blockIdx.z >> 4, h = blockIdx.z & 15;
    const float* src = (sel == 0 ? wq : (sel == 1 ? wk : wv)) + (size_t)h * DD * DHH;
    int d0 = blockIdx.x * 32, dh0 = blockIdx.y * 32;
    int tx = threadIdx.x, ty = threadIdx.y;
    #pragma unroll
    for (int j = 0; j < 4; j++)
        t[ty + j * 8][tx] = src[(size_t)(d0 + ty + j * 8) * DHH + dh0 + tx];
    __syncthreads();
    int nb = sel * DD + h * DHH + dh0;
    #pragma unroll
    for (int j = 0; j < 4; j++) {
        size_t o = (size_t)(nb + ty + j * 8) * DD + d0 + tx;
        th[o] = __float2half_rn(t[tx][ty + j * 8]);
    }
}

__global__ void transpose_sq_kernel(const float* __restrict__ w0, const float* __restrict__ w1,
                                    const float* __restrict__ w2,
                                    __half* __restrict__ t0h, __half* __restrict__ t1h,
                                    __half* __restrict__ t2h) {
    __shared__ float t[32][33];
    int z = blockIdx.z;
    const float* src = z == 0 ? w0 : (z == 1 ? w1 : w2);
    __half* dh = z == 0 ? t0h : (z == 1 ? t1h : t2h);
    int r0 = blockIdx.x * 32, c0 = blockIdx.y * 32;
    int tx = threadIdx.x, ty = threadIdx.y;
    #pragma unroll
    for (int j = 0; j < 4; j++)
        t[ty + j * 8][tx] = src[(size_t)(r0 + ty + j * 8) * DD + c0 + tx];
    __syncthreads();
    #pragma unroll
    for (int j = 0; j < 4; j++) {
        size_t o = (size_t)(c0 + ty + j * 8) * DD + r0 + tx;
        dh[o] = __float2half_rn(t[tx][ty + j * 8]);
    }
}

// ---------------- mma.sync fp16 GEMM: BK=32, 3-stage, early-issue ----------------
// C = A[M,K] @ B[N,K]^T. 128 threads, tile 64x128, occ 4.
#define GLDA 40
#define ATILE (64 * GLDA * 2)    // 5120
#define BTILE (128 * GLDA * 2)   // 10240
#define GSTG  (ATILE + BTILE)    // 15360
#define GSM   (3 * GSTG)         // 46080

__device__ __forceinline__ void g_load(uint32_t st,
    const __half* __restrict__ A, const __half* __restrict__ B,
    int brow, int bcol, int k0, int K, int tid)
{
    #pragma unroll
    for (int it = 0; it < 2; it++) {
        int g = tid + it * 128;
        int r = g >> 2, gi = g & 3;
        uint32_t so = (uint32_t)(r * GLDA + gi * 8) * 2;
        cpa16(st + so, A + (size_t)(brow + r) * K + k0 + gi * 8);
    }
    #pragma unroll
    for (int it = 0; it < 4; it++) {
        int g = tid + it * 128;
        int r = g >> 2, gi = g & 3;
        uint32_t so = (uint32_t)(r * GLDA + gi * 8) * 2;
        cpa16(st + ATILE + so, B + (size_t)(bcol + r) * K + k0 + gi * 8);
    }
}

template <int ADD, int RELU, int HOUT>
__global__ void __launch_bounds__(128, 4)
gemm_mma_kernel(const __half* __restrict__ A, const __half* __restrict__ B,
                float* __restrict__ Cf, __half* __restrict__ Ch,
                const float* __restrict__ R, int N, int K) {
    extern __shared__ char smg[];
    uint32_t sbase = smem_u32(smg);
    int tid = threadIdx.x, lane = tid & 31, wid = tid >> 5;
    int wn = wid * 32;
    int brow = blockIdx.y * 64, bcol = blockIdx.x * 128;
    int NC = K >> 5;

    float acc[4][4][4];
    #pragma unroll
    for (int i = 0; i < 4; i++)
        #pragma unroll
        for (int j = 0; j < 4; j++)
            #pragma unroll
            for (int e = 0; e < 4; e++) acc[i][j][e] = 0.f;

    g_load(sbase,        A, B, brow, bcol, 0,  K, tid); cpcommit();
    g_load(sbase + GSTG, A, B, brow, bcol, 32, K, tid); cpcommit();

    int aRow = lane & 15, aCol8 = (lane >> 4) * 8;
    int bnRow = (lane & 7) + ((lane >> 4) & 1) * 8;
    int bkCol = ((lane >> 3) & 1) * 8;

    uint32_t af[2][4][4];

    for (int c = 0; c < NC; c++) {
        if (c + 1 < NC) cpwait<1>(); else cpwait<0>();
        __syncthreads();
        // early-issue load for c+2: stage (c+2)%3 last read in chunk c-1, which
        // the barrier above proves complete.
        if (c + 2 < NC) {
            g_load(sbase + ((c + 2) % 3) * GSTG, A, B, brow, bcol, (c + 2) * 32, K, tid);
            cpcommit();
        }
        uint32_t sA = sbase + (c % 3) * GSTG;

        // preload A frags ks=0
        #pragma unroll
        for (int mt = 0; mt < 4; mt++) {
            uint32_t off = (uint32_t)((mt * 16 + aRow) * GLDA + aCol8) * 2;
            ldsm_x4(af[0][mt], sA + off);
        }

        #pragma unroll
        for (int ks = 0; ks < 2; ks++) {
            uint32_t bb[4][2];
            #pragma unroll
            for (int ntp = 0; ntp < 2; ntp++) {
                uint32_t off = (uint32_t)((wn + ntp * 16 + bnRow) * GLDA + ks * 16 + bkCol) * 2;
                ldsm_x4(&bb[ntp * 2][0], sA + ATILE + off);
            }
            if (ks == 0) {      // prefetch A frags for ks=1 under the MMAs
                #pragma unroll
                for (int mt = 0; mt < 4; mt++) {
                    uint32_t off = (uint32_t)((mt * 16 + aRow) * GLDA + 16 + aCol8) * 2;
                    ldsm_x4(af[1][mt], sA + off);
                }
            }
            #pragma unroll
            for (int mt = 0; mt < 4; mt++)
                #pragma unroll
                for (int nt = 0; nt < 4; nt++)
                    mma16816(acc[mt][nt], af[ks][mt], bb[nt]);
        }
    }

    int r0 = brow + (lane >> 2);
    int c0 = bcol + wn + (lane & 3) * 2;
    #pragma unroll
    for (int mt = 0; mt < 4; mt++)
        #pragma unroll
        for (int half = 0; half < 2; half++) {
            int row = r0 + mt * 16 + half * 8;
            #pragma unroll
            for (int nt = 0; nt < 4; nt++) {
                float vx = acc[mt][nt][half * 2], vy = acc[mt][nt][half * 2 + 1];
                size_t o = (size_t)row * N + c0 + nt * 8;
                if (ADD) { vx += R[o]; vy += R[o + 1]; }
                if (RELU) { vx = fmaxf(vx, 0.f); vy = fmaxf(vy, 0.f); }
                if (HOUT) {
                    *(uint32_t*)&Ch[o] = packh(vx, vy);
                } else {
                    *(float2*)&Cf[o] = make_float2(vx, vy);
                }
            }
        }
}

// ---------------- flash attention (single fp16) ----------------
#define FST 72
#define F_Q 0
#define F_ST0 9216
#define F_STG 18432           // per stage: K (9216) + V (9216)
#define F_SM (F_ST0 + 2 * F_STG)   // 46080

__device__ __forceinline__ void f_load_tile(uint32_t st,
    const __half* __restrict__ qkv, int b, int h, int krow, int tid)
{
    #pragma unroll
    for (int i = 0; i < 4; i++) {
        int g = tid + i * 128, r = g >> 3, gr = g & 7;
        size_t kro = (size_t)(b * SS + krow + r) * LD3 + DD + h * DHH + gr * 8;
        uint32_t dst = (uint32_t)(r * FST + gr * 8) * 2;
        cpa16(st + dst,        qkv + kro);        // K
        cpa16(st + 9216 + dst, qkv + kro + DD);   // V
    }
}

__global__ void __launch_bounds__(128, 4)
flash_mma_kernel(const __half* __restrict__ qkv, __half* __restrict__ ch) {
    extern __shared__ char smf[];
    uint32_t sb = smem_u32(smf);
    int tid = threadIdx.x, lane = tid & 31, w = tid >> 5;
    int b = blockIdx.z, h = blockIdx.y, q0 = blockIdx.x * 64;

    #pragma unroll
    for (int i = 0; i < 4; i++) {
        int g = tid + i * 128, r = g >> 3, gr = g & 7;
        size_t src = (size_t)(b * SS + q0 + r) * LD3 + h * DHH + gr * 8;
        uint32_t dst = (uint32_t)(r * FST + gr * 8) * 2;
        cpa16(sb + F_Q + dst, qkv + src);
    }
    cpcommit();
    f_load_tile(sb + F_ST0, qkv, b, h, 0, tid);
    cpcommit();

    cpwait<1>();
    __syncthreads();
    int lr = lane & 15, hc = (lane >> 4) * 8;
    uint32_t Qf[4][4];
    #pragma unroll
    for (int kk = 0; kk < 4; kk++) {
        uint32_t off = (uint32_t)((16 * w + lr) * FST + kk * 16 + hc) * 2;
        ldsm_x4(Qf[kk], sb + F_Q + off);
    }

    int bnRow = (lane & 7) + ((lane >> 4) & 1) * 8;
    int bkCol = ((lane >> 3) & 1) * 8;
    int vRow = (lane & 7) + ((lane >> 3) & 1) * 8;
    int vCol = (lane >> 4) * 8;

    float m0 = -1e30f, m1 = -1e30f, l0 = 0.f, l1 = 0.f;
    float ao[8][4];
    #pragma unroll
    for (int n = 0; n < 8; n++)
        #pragma unroll
        for (int e = 0; e < 4; e++) ao[n][e] = 0.f;

    for (int kb = 0; kb < SS; kb += 64) {
        int t = kb >> 6;
        cpwait<0>();
        __syncthreads();
        if (kb + 64 < SS) {
            f_load_tile(sb + F_ST0 + ((t + 1) & 1) * F_STG, qkv, b, h, kb + 64, tid);
            cpcommit();
        }
        uint32_t st = sb + F_ST0 + (t & 1) * F_STG;

        float s_[8][4];
        #pragma unroll
        for (int n = 0; n < 8; n++)
            #pragma unroll
            for (int e = 0; e < 4; e++) s_[n][e] = 0.f;
        #pragma unroll
        for (int kk = 0; kk < 4; kk++) {
            uint32_t bh[8][2];
            #pragma unroll
            for (int ntp = 0; ntp < 4; ntp++) {
                uint32_t off = (uint32_t)((ntp * 16 + bnRow) * FST + kk * 16 + bkCol) * 2;
                ldsm_x4(&bh[ntp * 2][0], st + off);
            }
            #pragma unroll
            for (int nt = 0; nt < 8; nt++) mma16816(s_[nt], Qf[kk], bh[nt]);
        }

        float tm0 = -1e30f, tm1 = -1e30f;
        #pragma unroll
        for (int n = 0; n < 8; n++) {
            #pragma unroll
            for (int e = 0; e < 4; e++) s_[n][e] *= 0.125f;
            tm0 = fmaxf(tm0, fmaxf(s_[n][0], s_[n][1]));
            tm1 = fmaxf(tm1, fmaxf(s_[n][2], s_[n][3]));
        }
        tm0 = fmaxf(tm0, __shfl_xor_sync(0xffffffffu, tm0, 1));
        tm0 = fmaxf(tm0, __shfl_xor_sync(0xffffffffu, tm0, 2));
        tm1 = fmaxf(tm1, __shfl_xor_sync(0xffffffffu, tm1, 1));
        tm1 = fmaxf(tm1, __shfl_xor_sync(0xffffffffu, tm1, 2));
        float mn0 = fmaxf(m0, tm0), mn1 = fmaxf(m1, tm1);
        float sc0 = __expf(m0 - mn0), sc1 = __expf(m1 - mn1);
        m0 = mn0; m1 = mn1;
        float ls0 = 0.f, ls1 = 0.f;
        #pragma unroll
        for (int n = 0; n < 8; n++) {
            s_[n][0] = __expf(s_[n][0] - mn0);
            s_[n][1] = __expf(s_[n][1] - mn0);
            s_[n][2] = __expf(s_[n][2] - mn1);
            s_[n][3] = __expf(s_[n][3] - mn1);
            ls0 += s_[n][0] + s_[n][1];
            ls1 += s_[n][2] + s_[n][3];
        }
        ls0 += __shfl_xor_sync(0xffffffffu, ls0, 1);
        ls0 += __shfl_xor_sync(0xffffffffu, ls0, 2);
        ls1 += __shfl_xor_sync(0xffffffffu, ls1, 1);
        ls1 += __shfl_xor_sync(0xffffffffu, ls1, 2);
        l0 = l0 * sc0 + ls0;
        l1 = l1 * sc1 + ls1;
        #pragma unroll
        for (int n = 0; n < 8; n++) {
            ao[n][0] *= sc0; ao[n][1] *= sc0;
            ao[n][2] *= sc1; ao[n][3] *= sc1;
        }

        #pragma unroll
        for (int k2 = 0; k2 < 4; k2++) {
            uint32_t pa[4];
            pa[0] = packh(s_[2 * k2][0],     s_[2 * k2][1]);
            pa[1] = packh(s_[2 * k2][2],     s_[2 * k2][3]);
            pa[2] = packh(s_[2 * k2 + 1][0], s_[2 * k2 + 1][1]);
            pa[3] = packh(s_[2 * k2 + 1][2], s_[2 * k2 + 1][3]);
            #pragma unroll
            for (int ntp = 0; ntp < 4; ntp++) {
                uint32_t bv[4];
                ldsm_x4t(bv, st + 9216
                         + (uint32_t)((k2 * 16 + vRow) * FST + ntp * 16 + vCol) * 2);
                mma16816(ao[ntp * 2],     pa, &bv[0]);
                mma16816(ao[ntp * 2 + 1], pa, &bv[2]);
            }
        }
    }

    float i0 = 1.0f / l0, i1 = 1.0f / l1;
    int row0 = b * SS + q0 + 16 * w + (lane >> 2);
    int cb = h * DHH + (lane & 3) * 2;
    #pragma unroll
    for (int nt = 0; nt < 8; nt++) {
        size_t o0 = (size_t)row0 * DD + cb + nt * 8;
        size_t o1 = (size_t)(row0 + 8) * DD + cb + nt * 8;
        *(uint32_t*)&ch[o0] = packh(ao[nt][0] * i0, ao[nt][1] * i0);
        *(uint32_t*)&ch[o1] = packh(ao[nt][2] * i1, ao[nt][3] * i1);
    }
}

// ---------------- launch ----------------
#define SYM(p, s) cudaGetSymbolAddress((void**)&p, s)

extern "C" void kernel_launch(void* const* d_in, const int* in_sizes, int n_in,
                              void* d_out, int out_size) {
    const float* x     = (const float*)d_in[0];
    const float* wq    = (const float*)d_in[1];
    const float* wk    = (const float*)d_in[2];
    const float* wv    = (const float*)d_in[3];
    const float* wo    = (const float*)d_in[4];
    const float* w1    = (const float*)d_in[5];
    const float* w2    = (const float*)d_in[6];
    const float* ln1_g = (const float*)d_in[7];
    const float* ln1_b = (const float*)d_in[8];
    const float* ln2_g = (const float*)d_in[9];
    const float* ln2_b = (const float*)d_in[10];
    const float* ln3_g = (const float*)d_in[11];
    const float* ln3_b = (const float*)d_in[12];
    float* out = (float*)d_out;

    float *p_attn, *p_ln2f, *p_res2;
    __half *p_ln1h, *p_ln2h, *p_ctxh, *p_f1h, *p_qkvh;
    __half *p_wqh, *p_woh, *p_w1h, *p_w2h;
    SYM(p_attn, g_attn); SYM(p_ln2f, g_ln2f); SYM(p_res2, g_res2);
    SYM(p_ln1h, g_ln1h); SYM(p_ln2h, g_ln2h);
    SYM(p_ctxh, g_ctxh); SYM(p_f1h, g_f1h); SYM(p_qkvh, g_qkvh);
    SYM(p_wqh, g_wqh); SYM(p_woh, g_woh); SYM(p_w1h, g_w1h); SYM(p_w2h, g_w2h);

    cudaFuncSetAttribute(gemm_mma_kernel<0,0,1>, cudaFuncAttributeMaxDynamicSharedMemorySize, GSM);
    cudaFuncSetAttribute(gemm_mma_kernel<1,0,0>, cudaFuncAttributeMaxDynamicSharedMemorySize, GSM);
    cudaFuncSetAttribute(gemm_mma_kernel<0,1,1>, cudaFuncAttributeMaxDynamicSharedMemorySize, GSM);
    cudaFuncSetAttribute(flash_mma_kernel, cudaFuncAttributeMaxDynamicSharedMemorySize, F_SM);

    transpose_qkv_kernel<<<dim3(DD / 32, DHH / 32, 48), dim3(32, 8)>>>(wq, wk, wv, p_wqh);
    transpose_sq_kernel<<<dim3(32, 32, 3), dim3(32, 8)>>>(wo, w1, w2, p_woh, p_w1h, p_w2h);

    layernorm_kernel<<<MM, 256>>>(x, ln1_g, ln1_b, nullptr, p_ln1h);
    gemm_mma_kernel<0,0,1><<<dim3(LD3 / 128, MM / 64), 128, GSM>>>(
        p_ln1h, p_wqh, nullptr, p_qkvh, nullptr, LD3, DD);
    flash_mma_kernel<<<dim3(SS / 64, HH, BB), 128, F_SM>>>(p_qkvh, p_ctxh);
    gemm_mma_kernel<1,0,0><<<dim3(DD / 128, MM / 64), 128, GSM>>>(
        p_ctxh, p_woh, p_attn, nullptr, x, DD, DD);
    layernorm_kernel<<<MM, 256>>>(p_attn, ln2_g, ln2_b, p_ln2f, p_ln2h);
    gemm_mma_kernel<0,1,1><<<dim3(DD / 128, MM / 64), 128, GSM>>>(
        p_ln2h, p_w1h, nullptr, p_f1h, nullptr, DD, DD);
    gemm_mma_kernel<1,0,0><<<dim3(DD / 128, MM / 64), 128, GSM>>>(
        p_f1h, p_w2h, p_res2, nullptr, p_ln2f, DD, DD);
    layernorm_kernel<<<MM, 256>>>(p_res2, ln3_g, ln3_b, out, nullptr);
}

// round 13
// speedup vs baseline: 1.0325x; 1.0325x over previous
#include <cuda_runtime.h>
#include <cuda_fp16.h>
#include <math.h>
#include <stdint.h>

#define BB 2
#define SS 2048
#define DD 1024
#define HH 16
#define DHH 64
#define MM (BB * SS)
#define LD3 (3 * DD)

// ---------------- scratch ----------------
__device__ float g_attn[MM * DD];
__device__ float g_ln2f[MM * DD];
__device__ float g_res2[MM * DD];

__device__ __half g_ln1h[MM * DD];
__device__ __half g_ln2h[MM * DD];
__device__ __half g_ctxh[MM * DD];
__device__ __half g_f1h [MM * DD];
__device__ __half g_qkvh[MM * LD3];
__device__ __half g_wqh[LD3 * DD];
__device__ __half g_woh[DD * DD];
__device__ __half g_w1h[DD * DD];
__device__ __half g_w2h[DD * DD];

// ---------------- helpers ----------------
__device__ __forceinline__ uint32_t smem_u32(const void* p) {
    uint32_t a;
    asm("{ .reg .u64 t; cvta.to.shared.u64 t, %1; cvt.u32.u64 %0, t; }" : "=r"(a) : "l"(p));
    return a;
}
__device__ __forceinline__ void cpa16(uint32_t dst, const void* src) {
    asm volatile("cp.async.cg.shared.global [%0], [%1], 16;" :: "r"(dst), "l"(src) : "memory");
}
__device__ __forceinline__ void cpcommit() { asm volatile("cp.async.commit_group;" ::: "memory"); }
template <int N> __device__ __forceinline__ void cpwait() {
    asm volatile("cp.async.wait_group %0;" :: "n"(N) : "memory");
}
__device__ __forceinline__ void ldsm_x4(uint32_t* r, uint32_t a) {
    asm volatile("ldmatrix.sync.aligned.m8n8.x4.shared.b16 {%0,%1,%2,%3}, [%4];"
        : "=r"(r[0]), "=r"(r[1]), "=r"(r[2]), "=r"(r[3]) : "r"(a));
}
__device__ __forceinline__ void ldsm_x4t(uint32_t* r, uint32_t a) {
    asm volatile("ldmatrix.sync.aligned.m8n8.x4.trans.shared.b16 {%0,%1,%2,%3}, [%4];"
        : "=r"(r[0]), "=r"(r[1]), "=r"(r[2]), "=r"(r[3]) : "r"(a));
}
__device__ __forceinline__ void mma16816(float* d, const uint32_t* a, const uint32_t* b) {
    asm volatile("mma.sync.aligned.m16n8k16.row.col.f32.f16.f16.f32 "
        "{%0,%1,%2,%3},{%4,%5,%6,%7},{%8,%9},{%0,%1,%2,%3};"
        : "+f"(d[0]), "+f"(d[1]), "+f"(d[2]), "+f"(d[3])
        : "r"(a[0]), "r"(a[1]), "r"(a[2]), "r"(a[3]), "r"(b[0]), "r"(b[1]));
}
__device__ __forceinline__ uint32_t packh(float a, float b) {
    __half2 t = __floats2half2_rn(a, b);
    return *(uint32_t*)&t;
}

// ---------------- layernorm ----------------
__device__ __forceinline__ float block_sum_256(float v, float* red) {
    #pragma unroll
    for (int o = 16; o; o >>= 1) v += __shfl_xor_sync(0xffffffffu, v, o);
    int w = threadIdx.x >> 5;
    if ((threadIdx.x & 31) == 0) red[w] = v;
    __syncthreads();
    if (threadIdx.x < 8) {
        v = red[threadIdx.x];
        #pragma unroll
        for (int o = 4; o; o >>= 1) v += __shfl_xor_sync(0xffu, v, o);
        if (threadIdx.x == 0) red[0] = v;
    }
    __syncthreads();
    float r = red[0];
    __syncthreads();
    return r;
}

__global__ void layernorm_kernel(const float* __restrict__ x,
                                 const float* __restrict__ g,
                                 const float* __restrict__ b,
                                 float* __restrict__ outf,
                                 __half* __restrict__ outh) {
    __shared__ float red[32];
    int row = blockIdx.x;
    const float* xr = x + (size_t)row * DD;
    float v[4], s = 0.f;
    #pragma unroll
    for (int i = 0; i < 4; i++) { v[i] = xr[threadIdx.x + i * 256]; s += v[i]; }
    float mean = block_sum_256(s, red) * (1.0f / DD);
    float sq = 0.f;
    #pragma unroll
    for (int i = 0; i < 4; i++) { float d = v[i] - mean; sq += d * d; }
    float inv = rsqrtf(block_sum_256(sq, red) * (1.0f / DD) + 1e-5f);
    #pragma unroll
    for (int i = 0; i < 4; i++) {
        int c = threadIdx.x + i * 256;
        float y = (v[i] - mean) * inv * g[c] + b[c];
        size_t o = (size_t)row * DD + c;
        if (outf) outf[o] = y;
        if (outh) outh[o] = __float2half_rn(y);
    }
}

// ---------------- weight transposes -> [N,K] single fp16 ----------------
__global__ void transpose_qkv_kernel(const float* __restrict__ wq, const float* __restrict__ wk,
                                     const float* __restrict__ wv,
                                     __half* __restrict__ th) {
    __shared__ float t[32][33];
    int sel = blockIdx.z >> 4, h = blockIdx.z & 15;
    const float* src = (sel == 0 ? wq : (sel == 1 ? wk : wv)) + (size_t)h * DD * DHH;
    int d0 = blockIdx.x * 32, dh0 = blockIdx.y * 32;
    int tx = threadIdx.x, ty = threadIdx.y;
    #pragma unroll
    for (int j = 0; j < 4; j++)
        t[ty + j * 8][tx] = src[(size_t)(d0 + ty + j * 8) * DHH + dh0 + tx];
    __syncthreads();
    int nb = sel * DD + h * DHH + dh0;
    #pragma unroll
    for (int j = 0; j < 4; j++) {
        size_t o = (size_t)(nb + ty + j * 8) * DD + d0 + tx;
        th[o] = __float2half_rn(t[tx][ty + j * 8]);
    }
}

__global__ void transpose_sq_kernel(const float* __restrict__ w0, const float* __restrict__ w1,
                                    const float* __restrict__ w2,
                                    __half* __restrict__ t0h, __half* __restrict__ t1h,
                                    __half* __restrict__ t2h) {
    __shared__ float t[32][33];
    int z = blockIdx.z;
    const float* src = z == 0 ? w0 : (z == 1 ? w1 : w2);
    __half* dh = z == 0 ? t0h : (z == 1 ? t1h : t2h);
    int r0 = blockIdx.x * 32, c0 = blockIdx.y * 32;
    int tx = threadIdx.x, ty = threadIdx.y;
    #pragma unroll
    for (int j = 0; j < 4; j++)
        t[ty + j * 8][tx] = src[(size_t)(r0 + ty + j * 8) * DD + c0 + tx];
    __syncthreads();
    #pragma unroll
    for (int j = 0; j < 4; j++) {
        size_t o = (size_t)(c0 + ty + j * 8) * DD + r0 + tx;
        dh[o] = __float2half_rn(t[tx][ty + j * 8]);
    }
}

// ---------------- mma.sync fp16 GEMM, BK=64, fragment-pipelined (R11 config) ----------------
#define GLDA 72                   // 64 k elems + 8 pad
#define ATILE (64 * GLDA * 2)     // 9216
#define BTILE (128 * GLDA * 2)    // 18432
#define GSTG  (ATILE + BTILE)     // 27648
#define GSM   (2 * GSTG)          // 55296

__device__ __forceinline__ void g_load(uint32_t st,
    const __half* __restrict__ A, const __half* __restrict__ B,
    int brow, int bcol, int k0, int K, int tid)
{
    #pragma unroll
    for (int it = 0; it < 4; it++) {           // A: 64 rows x 8 granules
        int g = tid + it * 128;
        int r = g >> 3, gi = g & 7;
        uint32_t so = (uint32_t)(r * GLDA + gi * 8) * 2;
        cpa16(st + so, A + (size_t)(brow + r) * K + k0 + gi * 8);
    }
    #pragma unroll
    for (int it = 0; it < 8; it++) {           // B: 128 rows x 8 granules
        int g = tid + it * 128;
        int r = g >> 3, gi = g & 7;
        uint32_t so = (uint32_t)(r * GLDA + gi * 8) * 2;
        cpa16(st + ATILE + so, B + (size_t)(bcol + r) * K + k0 + gi * 8);
    }
}

template <int ADD, int RELU, int HOUT>
__global__ void __launch_bounds__(128, 4)
gemm_mma_kernel(const __half* __restrict__ A, const __half* __restrict__ B,
                float* __restrict__ Cf, __half* __restrict__ Ch,
                const float* __restrict__ R, int N, int K) {
    extern __shared__ char smg[];
    uint32_t sbase = smem_u32(smg);
    int tid = threadIdx.x, lane = tid & 31, wid = tid >> 5;
    int wn = wid * 32;
    int brow = blockIdx.y * 64, bcol = blockIdx.x * 128;
    int NC = K >> 6;

    float acc[4][4][4];
    #pragma unroll
    for (int i = 0; i < 4; i++)
        #pragma unroll
        for (int j = 0; j < 4; j++)
            #pragma unroll
            for (int e = 0; e < 4; e++) acc[i][j][e] = 0.f;

    g_load(sbase, A, B, brow, bcol, 0, K, tid); cpcommit();

    int aRow = lane & 15, aCol8 = (lane >> 4) * 8;
    int bnRow = (lane & 7) + ((lane >> 4) & 1) * 8;
    int bkCol = ((lane >> 3) & 1) * 8;

    uint32_t af[2][4][4];   // A-fragment double buffer

    for (int c = 0; c < NC; c++) {
        cpwait<0>();
        __syncthreads();
        if (c + 1 < NC) {
            g_load(sbase + ((c + 1) & 1) * GSTG, A, B, brow, bcol, (c + 1) * 64, K, tid);
            cpcommit();
        }
        uint32_t sA = sbase + (c & 1) * GSTG;

        #pragma unroll
        for (int mt = 0; mt < 4; mt++) {
            uint32_t off = (uint32_t)((mt * 16 + aRow) * GLDA + aCol8) * 2;
            ldsm_x4(af[0][mt], sA + off);
        }

        #pragma unroll
        for (int ks = 0; ks < 4; ks++) {
            uint32_t bb[4][2];
            #pragma unroll
            for (int ntp = 0; ntp < 2; ntp++) {
                uint32_t off = (uint32_t)((wn + ntp * 16 + bnRow) * GLDA + ks * 16 + bkCol) * 2;
                ldsm_x4(&bb[ntp * 2][0], sA + ATILE + off);
            }
            if (ks < 3) {
                #pragma unroll
                for (int mt = 0; mt < 4; mt++) {
                    uint32_t off = (uint32_t)((mt * 16 + aRow) * GLDA + (ks + 1) * 16 + aCol8) * 2;
                    ldsm_x4(af[(ks + 1) & 1][mt], sA + off);
                }
            }
            #pragma unroll
            for (int mt = 0; mt < 4; mt++)
                #pragma unroll
                for (int nt = 0; nt < 4; nt++)
                    mma16816(acc[mt][nt], af[ks & 1][mt], bb[nt]);
        }
    }

    int r0 = brow + (lane >> 2);
    int c0 = bcol + wn + (lane & 3) * 2;
    #pragma unroll
    for (int mt = 0; mt < 4; mt++)
        #pragma unroll
        for (int half = 0; half < 2; half++) {
            int row = r0 + mt * 16 + half * 8;
            #pragma unroll
            for (int nt = 0; nt < 4; nt++) {
                float vx = acc[mt][nt][half * 2], vy = acc[mt][nt][half * 2 + 1];
                size_t o = (size_t)row * N + c0 + nt * 8;
                if (ADD) { vx += R[o]; vy += R[o + 1]; }
                if (RELU) { vx = fmaxf(vx, 0.f); vy = fmaxf(vy, 0.f); }
                if (HOUT) {
                    *(uint32_t*)&Ch[o] = packh(vx, vy);
                } else {
                    *(float2*)&Cf[o] = make_float2(vx, vy);
                }
            }
        }
}

// ---------------- flash attention: 128 queries/CTA, 256 threads ----------------
// 8 warps, each warp owns 16 query rows (identical per-warp code to before).
// K/V tiles shared by all 8 warps -> K/V global traffic halves.
#define FST 72
#define F_Q 0
#define F_QSZ 18432            // 128 rows x FST x 2B
#define F_ST0 F_QSZ
#define F_STG 18432            // per stage: K (9216) + V (9216)
#define F_SM (F_ST0 + 2 * F_STG)   // 55296

__device__ __forceinline__ void f_load_tile(uint32_t st,
    const __half* __restrict__ qkv, int b, int h, int krow, int tid)
{
    #pragma unroll
    for (int i = 0; i < 2; i++) {
        int g = tid + i * 256, r = g >> 3, gr = g & 7;
        size_t kro = (size_t)(b * SS + krow + r) * LD3 + DD + h * DHH + gr * 8;
        uint32_t dst = (uint32_t)(r * FST + gr * 8) * 2;
        cpa16(st + dst,        qkv + kro);        // K
        cpa16(st + 9216 + dst, qkv + kro + DD);   // V
    }
}

__global__ void __launch_bounds__(256, 2)
flash_mma_kernel(const __half* __restrict__ qkv, __half* __restrict__ ch) {
    extern __shared__ char smf[];
    uint32_t sb = smem_u32(smf);
    int tid = threadIdx.x, lane = tid & 31, w = tid >> 5;   // w in 0..7
    int b = blockIdx.z, h = blockIdx.y, q0 = blockIdx.x * 128;

    // load Q tile [128 x 64]
    #pragma unroll
    for (int i = 0; i < 4; i++) {
        int g = tid + i * 256, r = g >> 3, gr = g & 7;
        size_t src = (size_t)(b * SS + q0 + r) * LD3 + h * DHH + gr * 8;
        uint32_t dst = (uint32_t)(r * FST + gr * 8) * 2;
        cpa16(sb + F_Q + dst, qkv + src);
    }
    cpcommit();
    f_load_tile(sb + F_ST0, qkv, b, h, 0, tid);
    cpcommit();

    cpwait<1>();
    __syncthreads();
    int lr = lane & 15, hc = (lane >> 4) * 8;
    uint32_t Qf[4][4];
    #pragma unroll
    for (int kk = 0; kk < 4; kk++) {
        uint32_t off = (uint32_t)((16 * w + lr) * FST + kk * 16 + hc) * 2;
        ldsm_x4(Qf[kk], sb + F_Q + off);
    }

    int bnRow = (lane & 7) + ((lane >> 4) & 1) * 8;
    int bkCol = ((lane >> 3) & 1) * 8;
    int vRow = (lane & 7) + ((lane >> 3) & 1) * 8;
    int vCol = (lane >> 4) * 8;

    float m0 = -1e30f, m1 = -1e30f, l0 = 0.f, l1 = 0.f;
    float ao[8][4];
    #pragma unroll
    for (int n = 0; n < 8; n++)
        #pragma unroll
        for (int e = 0; e < 4; e++) ao[n][e] = 0.f;

    for (int kb = 0; kb < SS; kb += 64) {
        int t = kb >> 6;
        cpwait<0>();
        __syncthreads();
        if (kb + 64 < SS) {
            f_load_tile(sb + F_ST0 + ((t + 1) & 1) * F_STG, qkv, b, h, kb + 64, tid);
            cpcommit();
        }
        uint32_t st = sb + F_ST0 + (t & 1) * F_STG;

        float s_[8][4];
        #pragma unroll
        for (int n = 0; n < 8; n++)
            #pragma unroll
            for (int e = 0; e < 4; e++) s_[n][e] = 0.f;
        #pragma unroll
        for (int kk = 0; kk < 4; kk++) {
            uint32_t bh[8][2];
            #pragma unroll
            for (int ntp = 0; ntp < 4; ntp++) {
                uint32_t off = (uint32_t)((ntp * 16 + bnRow) * FST + kk * 16 + bkCol) * 2;
                ldsm_x4(&bh[ntp * 2][0], st + off);
            }
            #pragma unroll
            for (int nt = 0; nt < 8; nt++) mma16816(s_[nt], Qf[kk], bh[nt]);
        }

        float tm0 = -1e30f, tm1 = -1e30f;
        #pragma unroll
        for (int n = 0; n < 8; n++) {
            #pragma unroll
            for (int e = 0; e < 4; e++) s_[n][e] *= 0.125f;
            tm0 = fmaxf(tm0, fmaxf(s_[n][0], s_[n][1]));
            tm1 = fmaxf(tm1, fmaxf(s_[n][2], s_[n][3]));
        }
        tm0 = fmaxf(tm0, __shfl_xor_sync(0xffffffffu, tm0, 1));
        tm0 = fmaxf(tm0, __shfl_xor_sync(0xffffffffu, tm0, 2));
        tm1 = fmaxf(tm1, __shfl_xor_sync(0xffffffffu, tm1, 1));
        tm1 = fmaxf(tm1, __shfl_xor_sync(0xffffffffu, tm1, 2));
        float mn0 = fmaxf(m0, tm0), mn1 = fmaxf(m1, tm1);
        float sc0 = __expf(m0 - mn0), sc1 = __expf(m1 - mn1);
        m0 = mn0; m1 = mn1;
        float ls0 = 0.f, ls1 = 0.f;
        #pragma unroll
        for (int n = 0; n < 8; n++) {
            s_[n][0] = __expf(s_[n][0] - mn0);
            s_[n][1] = __expf(s_[n][1] - mn0);
            s_[n][2] = __expf(s_[n][2] - mn1);
            s_[n][3] = __expf(s_[n][3] - mn1);
            ls0 += s_[n][0] + s_[n][1];
            ls1 += s_[n][2] + s_[n][3];
        }
        ls0 += __shfl_xor_sync(0xffffffffu, ls0, 1);
        ls0 += __shfl_xor_sync(0xffffffffu, ls0, 2);
        ls1 += __shfl_xor_sync(0xffffffffu, ls1, 1);
        ls1 += __shfl_xor_sync(0xffffffffu, ls1, 2);
        l0 = l0 * sc0 + ls0;
        l1 = l1 * sc1 + ls1;
        #pragma unroll
        for (int n = 0; n < 8; n++) {
            ao[n][0] *= sc0; ao[n][1] *= sc0;
            ao[n][2] *= sc1; ao[n][3] *= sc1;
        }

        #pragma unroll
        for (int k2 = 0; k2 < 4; k2++) {
            uint32_t pa[4];
            pa[0] = packh(s_[2 * k2][0],     s_[2 * k2][1]);
            pa[1] = packh(s_[2 * k2][2],     s_[2 * k2][3]);
            pa[2] = packh(s_[2 * k2 + 1][0], s_[2 * k2 + 1][1]);
            pa[3] = packh(s_[2 * k2 + 1][2], s_[2 * k2 + 1][3]);
            #pragma unroll
            for (int ntp = 0; ntp < 4; ntp++) {
                uint32_t bv[4];
                ldsm_x4t(bv, st + 9216
                         + (uint32_t)((k2 * 16 + vRow) * FST + ntp * 16 + vCol) * 2);
                mma16816(ao[ntp * 2],     pa, &bv[0]);
                mma16816(ao[ntp * 2 + 1], pa, &bv[2]);
            }
        }
    }

    float i0 = 1.0f / l0, i1 = 1.0f / l1;
    int row0 = b * SS + q0 + 16 * w + (lane >> 2);
    int cb = h * DHH + (lane & 3) * 2;
    #pragma unroll
    for (int nt = 0; nt < 8; nt++) {
        size_t o0 = (size_t)row0 * DD + cb + nt * 8;
        size_t o1 = (size_t)(row0 + 8) * DD + cb + nt * 8;
        *(uint32_t*)&ch[o0] = packh(ao[nt][0] * i0, ao[nt][1] * i0);
        *(uint32_t*)&ch[o1] = packh(ao[nt][2] * i1, ao[nt][3] * i1);
    }
}

// ---------------- launch ----------------
#define SYM(p, s) cudaGetSymbolAddress((void**)&p, s)

extern "C" void kernel_launch(void* const* d_in, const int* in_sizes, int n_in,
                              void* d_out, int out_size) {
    const float* x     = (const float*)d_in[0];
    const float* wq    = (const float*)d_in[1];
    const float* wk    = (const float*)d_in[2];
    const float* wv    = (const float*)d_in[3];
    const float* wo    = (const float*)d_in[4];
    const float* w1    = (const float*)d_in[5];
    const float* w2    = (const float*)d_in[6];
    const float* ln1_g = (const float*)d_in[7];
    const float* ln1_b = (const float*)d_in[8];
    const float* ln2_g = (const float*)d_in[9];
    const float* ln2_b = (const float*)d_in[10];
    const float* ln3_g = (const float*)d_in[11];
    const float* ln3_b = (const float*)d_in[12];
    float* out = (float*)d_out;

    float *p_attn, *p_ln2f, *p_res2;
    __half *p_ln1h, *p_ln2h, *p_ctxh, *p_f1h, *p_qkvh;
    __half *p_wqh, *p_woh, *p_w1h, *p_w2h;
    SYM(p_attn, g_attn); SYM(p_ln2f, g_ln2f); SYM(p_res2, g_res2);
    SYM(p_ln1h, g_ln1h); SYM(p_ln2h, g_ln2h);
    SYM(p_ctxh, g_ctxh); SYM(p_f1h, g_f1h); SYM(p_qkvh, g_qkvh);
    SYM(p_wqh, g_wqh); SYM(p_woh, g_woh); SYM(p_w1h, g_w1h); SYM(p_w2h, g_w2h);

    cudaFuncSetAttribute(gemm_mma_kernel<0,0,1>, cudaFuncAttributeMaxDynamicSharedMemorySize, GSM);
    cudaFuncSetAttribute(gemm_mma_kernel<1,0,0>, cudaFuncAttributeMaxDynamicSharedMemorySize, GSM);
    cudaFuncSetAttribute(gemm_mma_kernel<0,1,1>, cudaFuncAttributeMaxDynamicSharedMemorySize, GSM);
    cudaFuncSetAttribute(flash_mma_kernel, cudaFuncAttributeMaxDynamicSharedMemorySize, F_SM);

    transpose_qkv_kernel<<<dim3(DD / 32, DHH / 32, 48), dim3(32, 8)>>>(wq, wk, wv, p_wqh);
    transpose_sq_kernel<<<dim3(32, 32, 3), dim3(32, 8)>>>(wo, w1, w2, p_woh, p_w1h, p_w2h);

    layernorm_kernel<<<MM, 256>>>(x, ln1_g, ln1_b, nullptr, p_ln1h);
    gemm_mma_kernel<0,0,1><<<dim3(LD3 / 128, MM / 64), 128, GSM>>>(
        p_ln1h, p_wqh, nullptr, p_qkvh, nullptr, LD3, DD);
    flash_mma_kernel<<<dim3(SS / 128, HH, BB), 256, F_SM>>>(p_qkvh, p_ctxh);
    gemm_mma_kernel<1,0,0><<<dim3(DD / 128, MM / 64), 128, GSM>>>(
        p_ctxh, p_woh, p_attn, nullptr, x, DD, DD);
    layernorm_kernel<<<MM, 256>>>(p_attn, ln2_g, ln2_b, p_ln2f, p_ln2h);
    gemm_mma_kernel<0,1,1><<<dim3(DD / 128, MM / 64), 128, GSM>>>(
        p_ln2h, p_w1h, nullptr, p_f1h, nullptr, DD, DD);
    gemm_mma_kernel<1,0,0><<<dim3(DD / 128, MM / 64), 128, GSM>>>(
        p_f1h, p_w2h, p_res2, nullptr, p_ln2f, DD, DD);
    layernorm_kernel<<<MM, 256>>>(p_res2, ln3_g, ln3_b, out, nullptr);
}

// round 14
// speedup vs baseline: 1.0909x; 1.0566x over previous
#include <cuda_runtime.h>
#include <cuda_fp16.h>
#include <math.h>
#include <stdint.h>

#define BB 2
#define SS 2048
#define DD 1024
#define HH 16
#define DHH 64
#define MM (BB * SS)
#define LD3 (3 * DD)

// ---------------- scratch ----------------
__device__ float g_attn[MM * DD];
__device__ float g_ln2f[MM * DD];
__device__ float g_res2[MM * DD];

__device__ __half g_ln1h[MM * DD];
__device__ __half g_ln2h[MM * DD];
__device__ __half g_ctxh[MM * DD];
__device__ __half g_f1h [MM * DD];
__device__ __half g_qkvh[MM * LD3];
__device__ __half g_wqh[LD3 * DD];
__device__ __half g_woh[DD * DD];
__device__ __half g_w1h[DD * DD];
__device__ __half g_w2h[DD * DD];

// ---------------- helpers ----------------
__device__ __forceinline__ uint32_t smem_u32(const void* p) {
    uint32_t a;
    asm("{ .reg .u64 t; cvta.to.shared.u64 t, %1; cvt.u32.u64 %0, t; }" : "=r"(a) : "l"(p));
    return a;
}
__device__ __forceinline__ void cpa16(uint32_t dst, const void* src) {
    asm volatile("cp.async.cg.shared.global [%0], [%1], 16;" :: "r"(dst), "l"(src) : "memory");
}
__device__ __forceinline__ void cpcommit() { asm volatile("cp.async.commit_group;" ::: "memory"); }
template <int N> __device__ __forceinline__ void cpwait() {
    asm volatile("cp.async.wait_group %0;" :: "n"(N) : "memory");
}
__device__ __forceinline__ void ldsm_x4(uint32_t* r, uint32_t a) {
    asm volatile("ldmatrix.sync.aligned.m8n8.x4.shared.b16 {%0,%1,%2,%3}, [%4];"
        : "=r"(r[0]), "=r"(r[1]), "=r"(r[2]), "=r"(r[3]) : "r"(a));
}
__device__ __forceinline__ void ldsm_x4t(uint32_t* r, uint32_t a) {
    asm volatile("ldmatrix.sync.aligned.m8n8.x4.trans.shared.b16 {%0,%1,%2,%3}, [%4];"
        : "=r"(r[0]), "=r"(r[1]), "=r"(r[2]), "=r"(r[3]) : "r"(a));
}
__device__ __forceinline__ void mma16816(float* d, const uint32_t* a, const uint32_t* b) {
    asm volatile("mma.sync.aligned.m16n8k16.row.col.f32.f16.f16.f32 "
        "{%0,%1,%2,%3},{%4,%5,%6,%7},{%8,%9},{%0,%1,%2,%3};"
        : "+f"(d[0]), "+f"(d[1]), "+f"(d[2]), "+f"(d[3])
        : "r"(a[0]), "r"(a[1]), "r"(a[2]), "r"(a[3]), "r"(b[0]), "r"(b[1]));
}
__device__ __forceinline__ uint32_t packh(float a, float b) {
    __half2 t = __floats2half2_rn(a, b);
    return *(uint32_t*)&t;
}

// ---------------- layernorm ----------------
__device__ __forceinline__ float block_sum_256(float v, float* red) {
    #pragma unroll
    for (int o = 16; o; o >>= 1) v += __shfl_xor_sync(0xffffffffu, v, o);
    int w = threadIdx.x >> 5;
    if ((threadIdx.x & 31) == 0) red[w] = v;
    __syncthreads();
    if (threadIdx.x < 8) {
        v = red[threadIdx.x];
        #pragma unroll
        for (int o = 4; o; o >>= 1) v += __shfl_xor_sync(0xffu, v, o);
        if (threadIdx.x == 0) red[0] = v;
    }
    __syncthreads();
    float r = red[0];
    __syncthreads();
    return r;
}

__global__ void layernorm_kernel(const float* __restrict__ x,
                                 const float* __restrict__ g,
                                 const float* __restrict__ b,
                                 float* __restrict__ outf,
                                 __half* __restrict__ outh) {
    __shared__ float red[32];
    int row = blockIdx.x;
    const float* xr = x + (size_t)row * DD;
    float v[4], s = 0.f;
    #pragma unroll
    for (int i = 0; i < 4; i++) { v[i] = xr[threadIdx.x + i * 256]; s += v[i]; }
    float mean = block_sum_256(s, red) * (1.0f / DD);
    float sq = 0.f;
    #pragma unroll
    for (int i = 0; i < 4; i++) { float d = v[i] - mean; sq += d * d; }
    float inv = rsqrtf(block_sum_256(sq, red) * (1.0f / DD) + 1e-5f);
    #pragma unroll
    for (int i = 0; i < 4; i++) {
        int c = threadIdx.x + i * 256;
        float y = (v[i] - mean) * inv * g[c] + b[c];
        size_t o = (size_t)row * DD + c;
        if (outf) outf[o] = y;
        if (outh) outh[o] = __float2half_rn(y);
    }
}

// ---------------- weight transposes -> [N,K] single fp16 ----------------
__global__ void transpose_qkv_kernel(const float* __restrict__ wq, const float* __restrict__ wk,
                                     const float* __restrict__ wv,
                                     __half* __restrict__ th) {
    __shared__ float t[32][33];
    int sel = blockIdx.z >> 4, h = blockIdx.z & 15;
    const float* src = (sel == 0 ? wq : (sel == 1 ? wk : wv)) + (size_t)h * DD * DHH;
    int d0 = blockIdx.x * 32, dh0 = blockIdx.y * 32;
    int tx = threadIdx.x, ty = threadIdx.y;
    #pragma unroll
    for (int j = 0; j < 4; j++)
        t[ty + j * 8][tx] = src[(size_t)(d0 + ty + j * 8) * DHH + dh0 + tx];
    __syncthreads();
    int nb = sel * DD + h * DHH + dh0;
    #pragma unroll
    for (int j = 0; j < 4; j++) {
        size_t o = (size_t)(nb + ty + j * 8) * DD + d0 + tx;
        th[o] = __float2half_rn(t[tx][ty + j * 8]);
    }
}

__global__ void transpose_sq_kernel(const float* __restrict__ w0, const float* __restrict__ w1,
                                    const float* __restrict__ w2,
                                    __half* __restrict__ t0h, __half* __restrict__ t1h,
                                    __half* __restrict__ t2h) {
    __shared__ float t[32][33];
    int z = blockIdx.z;
    const float* src = z == 0 ? w0 : (z == 1 ? w1 : w2);
    __half* dh = z == 0 ? t0h : (z == 1 ? t1h : t2h);
    int r0 = blockIdx.x * 32, c0 = blockIdx.y * 32;
    int tx = threadIdx.x, ty = threadIdx.y;
    #pragma unroll
    for (int j = 0; j < 4; j++)
        t[ty + j * 8][tx] = src[(size_t)(r0 + ty + j * 8) * DD + c0 + tx];
    __syncthreads();
    #pragma unroll
    for (int j = 0; j < 4; j++) {
        size_t o = (size_t)(c0 + ty + j * 8) * DD + r0 + tx;
        dh[o] = __float2half_rn(t[tx][ty + j * 8]);
    }
}

// ---------------- mma.sync fp16 GEMM: CTA 64x256, warp tile 64x64, BK=64 ----------------
// 128 threads (4 warps, N-split), 2 CTAs/SM, A-frag double buffer.
#define GLDA 72                   // 64 k elems + 8 pad
#define ATILE (64 * GLDA * 2)     // 9216
#define BTILE (256 * GLDA * 2)    // 36864
#define GSTG  (ATILE + BTILE)     // 46080
#define GSM   (2 * GSTG)          // 92160

__device__ __forceinline__ void g_load(uint32_t st,
    const __half* __restrict__ A, const __half* __restrict__ B,
    int brow, int bcol, int k0, int K, int tid)
{
    #pragma unroll
    for (int it = 0; it < 4; it++) {           // A: 64 rows x 8 granules
        int g = tid + it * 128;
        int r = g >> 3, gi = g & 7;
        uint32_t so = (uint32_t)(r * GLDA + gi * 8) * 2;
        cpa16(st + so, A + (size_t)(brow + r) * K + k0 + gi * 8);
    }
    #pragma unroll
    for (int it = 0; it < 16; it++) {          // B: 256 rows x 8 granules
        int g = tid + it * 128;
        int r = g >> 3, gi = g & 7;
        uint32_t so = (uint32_t)(r * GLDA + gi * 8) * 2;
        cpa16(st + ATILE + so, B + (size_t)(bcol + r) * K + k0 + gi * 8);
    }
}

template <int ADD, int RELU, int HOUT>
__global__ void __launch_bounds__(128, 2)
gemm_mma_kernel(const __half* __restrict__ A, const __half* __restrict__ B,
                float* __restrict__ Cf, __half* __restrict__ Ch,
                const float* __restrict__ R, int N, int K) {
    extern __shared__ char smg[];
    uint32_t sbase = smem_u32(smg);
    int tid = threadIdx.x, lane = tid & 31, wid = tid >> 5;
    int wn = wid * 64;
    int brow = blockIdx.y * 64, bcol = blockIdx.x * 256;
    int NC = K >> 6;

    float acc[4][8][4];
    #pragma unroll
    for (int i = 0; i < 4; i++)
        #pragma unroll
        for (int j = 0; j < 8; j++)
            #pragma unroll
            for (int e = 0; e < 4; e++) acc[i][j][e] = 0.f;

    g_load(sbase, A, B, brow, bcol, 0, K, tid); cpcommit();

    int aRow = lane & 15, aCol8 = (lane >> 4) * 8;
    int bnRow = (lane & 7) + ((lane >> 4) & 1) * 8;
    int bkCol = ((lane >> 3) & 1) * 8;

    uint32_t af[2][4][4];   // A-fragment double buffer

    for (int c = 0; c < NC; c++) {
        cpwait<0>();
        __syncthreads();
        if (c + 1 < NC) {
            g_load(sbase + ((c + 1) & 1) * GSTG, A, B, brow, bcol, (c + 1) * 64, K, tid);
            cpcommit();
        }
        uint32_t sA = sbase + (c & 1) * GSTG;

        #pragma unroll
        for (int mt = 0; mt < 4; mt++) {
            uint32_t off = (uint32_t)((mt * 16 + aRow) * GLDA + aCol8) * 2;
            ldsm_x4(af[0][mt], sA + off);
        }

        #pragma unroll
        for (int ks = 0; ks < 4; ks++) {
            uint32_t bb[8][2];
            #pragma unroll
            for (int ntp = 0; ntp < 4; ntp++) {
                uint32_t off = (uint32_t)((wn + ntp * 16 + bnRow) * GLDA + ks * 16 + bkCol) * 2;
                ldsm_x4(&bb[ntp * 2][0], sA + ATILE + off);
            }
            if (ks < 3) {
                #pragma unroll
                for (int mt = 0; mt < 4; mt++) {
                    uint32_t off = (uint32_t)((mt * 16 + aRow) * GLDA + (ks + 1) * 16 + aCol8) * 2;
                    ldsm_x4(af[(ks + 1) & 1][mt], sA + off);
                }
            }
            #pragma unroll
            for (int mt = 0; mt < 4; mt++)
                #pragma unroll
                for (int nt = 0; nt < 8; nt++)
                    mma16816(acc[mt][nt], af[ks & 1][mt], bb[nt]);
        }
    }

    int r0 = brow + (lane >> 2);
    int c0 = bcol + wn + (lane & 3) * 2;
    #pragma unroll
    for (int mt = 0; mt < 4; mt++)
        #pragma unroll
        for (int half = 0; half < 2; half++) {
            int row = r0 + mt * 16 + half * 8;
            #pragma unroll
            for (int nt = 0; nt < 8; nt++) {
                float vx = acc[mt][nt][half * 2], vy = acc[mt][nt][half * 2 + 1];
                size_t o = (size_t)row * N + c0 + nt * 8;
                if (ADD) { vx += R[o]; vy += R[o + 1]; }
                if (RELU) { vx = fmaxf(vx, 0.f); vy = fmaxf(vy, 0.f); }
                if (HOUT) {
                    *(uint32_t*)&Ch[o] = packh(vx, vy);
                } else {
                    *(float2*)&Cf[o] = make_float2(vx, vy);
                }
            }
        }
}

// ---------------- flash attention (R11 config: 64q, 128 threads, occ 4) ----------------
#define FST 72
#define F_Q 0
#define F_ST0 9216
#define F_STG 18432           // per stage: K (9216) + V (9216)
#define F_SM (F_ST0 + 2 * F_STG)   // 46080

__device__ __forceinline__ void f_load_tile(uint32_t st,
    const __half* __restrict__ qkv, int b, int h, int krow, int tid)
{
    #pragma unroll
    for (int i = 0; i < 4; i++) {
        int g = tid + i * 128, r = g >> 3, gr = g & 7;
        size_t kro = (size_t)(b * SS + krow + r) * LD3 + DD + h * DHH + gr * 8;
        uint32_t dst = (uint32_t)(r * FST + gr * 8) * 2;
        cpa16(st + dst,        qkv + kro);        // K
        cpa16(st + 9216 + dst, qkv + kro + DD);   // V
    }
}

__global__ void __launch_bounds__(128, 4)
flash_mma_kernel(const __half* __restrict__ qkv, __half* __restrict__ ch) {
    extern __shared__ char smf[];
    uint32_t sb = smem_u32(smf);
    int tid = threadIdx.x, lane = tid & 31, w = tid >> 5;
    int b = blockIdx.z, h = blockIdx.y, q0 = blockIdx.x * 64;

    #pragma unroll
    for (int i = 0; i < 4; i++) {
        int g = tid + i * 128, r = g >> 3, gr = g & 7;
        size_t src = (size_t)(b * SS + q0 + r) * LD3 + h * DHH + gr * 8;
        uint32_t dst = (uint32_t)(r * FST + gr * 8) * 2;
        cpa16(sb + F_Q + dst, qkv + src);
    }
    cpcommit();
    f_load_tile(sb + F_ST0, qkv, b, h, 0, tid);
    cpcommit();

    cpwait<1>();
    __syncthreads();
    int lr = lane & 15, hc = (lane >> 4) * 8;
    uint32_t Qf[4][4];
    #pragma unroll
    for (int kk = 0; kk < 4; kk++) {
        uint32_t off = (uint32_t)((16 * w + lr) * FST + kk * 16 + hc) * 2;
        ldsm_x4(Qf[kk], sb + F_Q + off);
    }

    int bnRow = (lane & 7) + ((lane >> 4) & 1) * 8;
    int bkCol = ((lane >> 3) & 1) * 8;
    int vRow = (lane & 7) + ((lane >> 3) & 1) * 8;
    int vCol = (lane >> 4) * 8;

    float m0 = -1e30f, m1 = -1e30f, l0 = 0.f, l1 = 0.f;
    float ao[8][4];
    #pragma unroll
    for (int n = 0; n < 8; n++)
        #pragma unroll
        for (int e = 0; e < 4; e++) ao[n][e] = 0.f;

    for (int kb = 0; kb < SS; kb += 64) {
        int t = kb >> 6;
        cpwait<0>();
        __syncthreads();
        if (kb + 64 < SS) {
            f_load_tile(sb + F_ST0 + ((t + 1) & 1) * F_STG, qkv, b, h, kb + 64, tid);
            cpcommit();
        }
        uint32_t st = sb + F_ST0 + (t & 1) * F_STG;

        float s_[8][4];
        #pragma unroll
        for (int n = 0; n < 8; n++)
            #pragma unroll
            for (int e = 0; e < 4; e++) s_[n][e] = 0.f;
        #pragma unroll
        for (int kk = 0; kk < 4; kk++) {
            uint32_t bh[8][2];
            #pragma unroll
            for (int ntp = 0; ntp < 4; ntp++) {
                uint32_t off = (uint32_t)((ntp * 16 + bnRow) * FST + kk * 16 + bkCol) * 2;
                ldsm_x4(&bh[ntp * 2][0], st + off);
            }
            #pragma unroll
            for (int nt = 0; nt < 8; nt++) mma16816(s_[nt], Qf[kk], bh[nt]);
        }

        float tm0 = -1e30f, tm1 = -1e30f;
        #pragma unroll
        for (int n = 0; n < 8; n++) {
            #pragma unroll
            for (int e = 0; e < 4; e++) s_[n][e] *= 0.125f;
            tm0 = fmaxf(tm0, fmaxf(s_[n][0], s_[n][1]));
            tm1 = fmaxf(tm1, fmaxf(s_[n][2], s_[n][3]));
        }
        tm0 = fmaxf(tm0, __shfl_xor_sync(0xffffffffu, tm0, 1));
        tm0 = fmaxf(tm0, __shfl_xor_sync(0xffffffffu, tm0, 2));
        tm1 = fmaxf(tm1, __shfl_xor_sync(0xffffffffu, tm1, 1));
        tm1 = fmaxf(tm1, __shfl_xor_sync(0xffffffffu, tm1, 2));
        float mn0 = fmaxf(m0, tm0), mn1 = fmaxf(m1, tm1);
        float sc0 = __expf(m0 - mn0), sc1 = __expf(m1 - mn1);
        m0 = mn0; m1 = mn1;
        float ls0 = 0.f, ls1 = 0.f;
        #pragma unroll
        for (int n = 0; n < 8; n++) {
            s_[n][0] = __expf(s_[n][0] - mn0);
            s_[n][1] = __expf(s_[n][1] - mn0);
            s_[n][2] = __expf(s_[n][2] - mn1);
            s_[n][3] = __expf(s_[n][3] - mn1);
            ls0 += s_[n][0] + s_[n][1];
            ls1 += s_[n][2] + s_[n][3];
        }
        ls0 += __shfl_xor_sync(0xffffffffu, ls0, 1);
        ls0 += __shfl_xor_sync(0xffffffffu, ls0, 2);
        ls1 += __shfl_xor_sync(0xffffffffu, ls1, 1);
        ls1 += __shfl_xor_sync(0xffffffffu, ls1, 2);
        l0 = l0 * sc0 + ls0;
        l1 = l1 * sc1 + ls1;
        #pragma unroll
        for (int n = 0; n < 8; n++) {
            ao[n][0] *= sc0; ao[n][1] *= sc0;
            ao[n][2] *= sc1; ao[n][3] *= sc1;
        }

        #pragma unroll
        for (int k2 = 0; k2 < 4; k2++) {
            uint32_t pa[4];
            pa[0] = packh(s_[2 * k2][0],     s_[2 * k2][1]);
            pa[1] = packh(s_[2 * k2][2],     s_[2 * k2][3]);
            pa[2] = packh(s_[2 * k2 + 1][0], s_[2 * k2 + 1][1]);
            pa[3] = packh(s_[2 * k2 + 1][2], s_[2 * k2 + 1][3]);
            #pragma unroll
            for (int ntp = 0; ntp < 4; ntp++) {
                uint32_t bv[4];
                ldsm_x4t(bv, st + 9216
                         + (uint32_t)((k2 * 16 + vRow) * FST + ntp * 16 + vCol) * 2);
                mma16816(ao[ntp * 2],     pa, &bv[0]);
                mma16816(ao[ntp * 2 + 1], pa, &bv[2]);
            }
        }
    }

    float i0 = 1.0f / l0, i1 = 1.0f / l1;
    int row0 = b * SS + q0 + 16 * w + (lane >> 2);
    int cb = h * DHH + (lane & 3) * 2;
    #pragma unroll
    for (int nt = 0; nt < 8; nt++) {
        size_t o0 = (size_t)row0 * DD + cb + nt * 8;
        size_t o1 = (size_t)(row0 + 8) * DD + cb + nt * 8;
        *(uint32_t*)&ch[o0] = packh(ao[nt][0] * i0, ao[nt][1] * i0);
        *(uint32_t*)&ch[o1] = packh(ao[nt][2] * i1, ao[nt][3] * i1);
    }
}

// ---------------- launch ----------------
#define SYM(p, s) cudaGetSymbolAddress((void**)&p, s)

extern "C" void kernel_launch(void* const* d_in, const int* in_sizes, int n_in,
                              void* d_out, int out_size) {
    const float* x     = (const float*)d_in[0];
    const float* wq    = (const float*)d_in[1];
    const float* wk    = (const float*)d_in[2];
    const float* wv    = (const float*)d_in[3];
    const float* wo    = (const float*)d_in[4];
    const float* w1    = (const float*)d_in[5];
    const float* w2    = (const float*)d_in[6];
    const float* ln1_g = (const float*)d_in[7];
    const float* ln1_b = (const float*)d_in[8];
    const float* ln2_g = (const float*)d_in[9];
    const float* ln2_b = (const float*)d_in[10];
    const float* ln3_g = (const float*)d_in[11];
    const float* ln3_b = (const float*)d_in[12];
    float* out = (float*)d_out;

    float *p_attn, *p_ln2f, *p_res2;
    __half *p_ln1h, *p_ln2h, *p_ctxh, *p_f1h, *p_qkvh;
    __half *p_wqh, *p_woh, *p_w1h, *p_w2h;
    SYM(p_attn, g_attn); SYM(p_ln2f, g_ln2f); SYM(p_res2, g_res2);
    SYM(p_ln1h, g_ln1h); SYM(p_ln2h, g_ln2h);
    SYM(p_ctxh, g_ctxh); SYM(p_f1h, g_f1h); SYM(p_qkvh, g_qkvh);
    SYM(p_wqh, g_wqh); SYM(p_woh, g_woh); SYM(p_w1h, g_w1h); SYM(p_w2h, g_w2h);

    cudaFuncSetAttribute(gemm_mma_kernel<0,0,1>, cudaFuncAttributeMaxDynamicSharedMemorySize, GSM);
    cudaFuncSetAttribute(gemm_mma_kernel<1,0,0>, cudaFuncAttributeMaxDynamicSharedMemorySize, GSM);
    cudaFuncSetAttribute(gemm_mma_kernel<0,1,1>, cudaFuncAttributeMaxDynamicSharedMemorySize, GSM);
    cudaFuncSetAttribute(flash_mma_kernel, cudaFuncAttributeMaxDynamicSharedMemorySize, F_SM);

    transpose_qkv_kernel<<<dim3(DD / 32, DHH / 32, 48), dim3(32, 8)>>>(wq, wk, wv, p_wqh);
    transpose_sq_kernel<<<dim3(32, 32, 3), dim3(32, 8)>>>(wo, w1, w2, p_woh, p_w1h, p_w2h);

    layernorm_kernel<<<MM, 256>>>(x, ln1_g, ln1_b, nullptr, p_ln1h);
    gemm_mma_kernel<0,0,1><<<dim3(LD3 / 256, MM / 64), 128, GSM>>>(
        p_ln1h, p_wqh, nullptr, p_qkvh, nullptr, LD3, DD);
    flash_mma_kernel<<<dim3(SS / 64, HH, BB), 128, F_SM>>>(p_qkvh, p_ctxh);
    gemm_mma_kernel<1,0,0><<<dim3(DD / 256, MM / 64), 128, GSM>>>(
        p_ctxh, p_woh, p_attn, nullptr, x, DD, DD);
    layernorm_kernel<<<MM, 256>>>(p_attn, ln2_g, ln2_b, p_ln2f, p_ln2h);
    gemm_mma_kernel<0,1,1><<<dim3(DD / 256, MM / 64), 128, GSM>>>(
        p_ln2h, p_w1h, nullptr, p_f1h, nullptr, DD, DD);
    gemm_mma_kernel<1,0,0><<<dim3(DD / 256, MM / 64), 128, GSM>>>(
        p_f1h, p_w2h, p_res2, nullptr, p_ln2f, DD, DD);
    layernorm_kernel<<<MM, 256>>>(p_res2, ln3_g, ln3_b, out, nullptr);
}

// round 15
// speedup vs baseline: 1.1034x; 1.0114x over previous
#include <cuda_runtime.h>
#include <cuda_fp16.h>
#include <math.h>
#include <stdint.h>

#define BB 2
#define SS 2048
#define DD 1024
#define HH 16
#define DHH 64
#define MM (BB * SS)
#define LD3 (3 * DD)

// ---------------- scratch ----------------
__device__ float g_attn[MM * DD];
__device__ float g_ln2f[MM * DD];
__device__ float g_res2[MM * DD];

__device__ __half g_ln1h[MM * DD];
__device__ __half g_ln2h[MM * DD];
__device__ __half g_ctxh[MM * DD];
__device__ __half g_f1h [MM * DD];
__device__ __half g_qkvh[MM * LD3];
__device__ __half g_wqh[LD3 * DD];
__device__ __half g_woh[DD * DD];
__device__ __half g_w1h[DD * DD];
__device__ __half g_w2h[DD * DD];

// ---------------- helpers ----------------
__device__ __forceinline__ uint32_t smem_u32(const void* p) {
    uint32_t a;
    asm("{ .reg .u64 t; cvta.to.shared.u64 t, %1; cvt.u32.u64 %0, t; }" : "=r"(a) : "l"(p));
    return a;
}
__device__ __forceinline__ void cpa16(uint32_t dst, const void* src) {
    asm volatile("cp.async.cg.shared.global [%0], [%1], 16;" :: "r"(dst), "l"(src) : "memory");
}
__device__ __forceinline__ void cpcommit() { asm volatile("cp.async.commit_group;" ::: "memory"); }
template <int N> __device__ __forceinline__ void cpwait() {
    asm volatile("cp.async.wait_group %0;" :: "n"(N) : "memory");
}
__device__ __forceinline__ void ldsm_x4(uint32_t* r, uint32_t a) {
    asm volatile("ldmatrix.sync.aligned.m8n8.x4.shared.b16 {%0,%1,%2,%3}, [%4];"
        : "=r"(r[0]), "=r"(r[1]), "=r"(r[2]), "=r"(r[3]) : "r"(a));
}
__device__ __forceinline__ void ldsm_x4t(uint32_t* r, uint32_t a) {
    asm volatile("ldmatrix.sync.aligned.m8n8.x4.trans.shared.b16 {%0,%1,%2,%3}, [%4];"
        : "=r"(r[0]), "=r"(r[1]), "=r"(r[2]), "=r"(r[3]) : "r"(a));
}
__device__ __forceinline__ void mma16816(float* d, const uint32_t* a, const uint32_t* b) {
    asm volatile("mma.sync.aligned.m16n8k16.row.col.f32.f16.f16.f32 "
        "{%0,%1,%2,%3},{%4,%5,%6,%7},{%8,%9},{%0,%1,%2,%3};"
        : "+f"(d[0]), "+f"(d[1]), "+f"(d[2]), "+f"(d[3])
        : "r"(a[0]), "r"(a[1]), "r"(a[2]), "r"(a[3]), "r"(b[0]), "r"(b[1]));
}
__device__ __forceinline__ uint32_t packh(float a, float b) {
    __half2 t = __floats2half2_rn(a, b);
    return *(uint32_t*)&t;
}

// ---------------- layernorm (vectorized float4) ----------------
__device__ __forceinline__ float block_sum_256(float v, float* red) {
    #pragma unroll
    for (int o = 16; o; o >>= 1) v += __shfl_xor_sync(0xffffffffu, v, o);
    int w = threadIdx.x >> 5;
    if ((threadIdx.x & 31) == 0) red[w] = v;
    __syncthreads();
    if (threadIdx.x < 8) {
        v = red[threadIdx.x];
        #pragma unroll
        for (int o = 4; o; o >>= 1) v += __shfl_xor_sync(0xffu, v, o);
        if (threadIdx.x == 0) red[0] = v;
    }
    __syncthreads();
    float r = red[0];
    __syncthreads();
    return r;
}

__global__ void layernorm_kernel(const float* __restrict__ x,
                                 const float* __restrict__ g,
                                 const float* __restrict__ b,
                                 float* __restrict__ outf,
                                 __half* __restrict__ outh) {
    __shared__ float red[32];
    int row = blockIdx.x;
    int t = threadIdx.x;
    float4 v = ((const float4*)(x + (size_t)row * DD))[t];
    float s = v.x + v.y + v.z + v.w;
    float mean = block_sum_256(s, red) * (1.0f / DD);
    float dx = v.x - mean, dy = v.y - mean, dz = v.z - mean, dw = v.w - mean;
    float sq = dx * dx + dy * dy + dz * dz + dw * dw;
    float inv = rsqrtf(block_sum_256(sq, red) * (1.0f / DD) + 1e-5f);
    float4 gg = ((const float4*)g)[t];
    float4 bb = ((const float4*)b)[t];
    float y0 = dx * inv * gg.x + bb.x;
    float y1 = dy * inv * gg.y + bb.y;
    float y2 = dz * inv * gg.z + bb.z;
    float y3 = dw * inv * gg.w + bb.w;
    size_t o4 = (size_t)row * (DD / 4) + t;
    if (outf) ((float4*)outf)[o4] = make_float4(y0, y1, y2, y3);
    if (outh) {
        uint2 hp;
        hp.x = packh(y0, y1);
        hp.y = packh(y2, y3);
        ((uint2*)outh)[o4] = hp;
    }
}

// ---------------- fused weight transpose -> [N,K] single fp16 ----------------
// z in [0,48): wq/wk/wv head-tiles;  z in [48,144): wo/w1/w2 32x32 tiles (32 per matrix)
__global__ void transpose_all_kernel(const float* __restrict__ wq, const float* __restrict__ wk,
                                     const float* __restrict__ wv, const float* __restrict__ w0,
                                     const float* __restrict__ w1, const float* __restrict__ w2,
                                     __half* __restrict__ thq,
                                     __half* __restrict__ t0h, __half* __restrict__ t1h,
                                     __half* __restrict__ t2h) {
    __shared__ float t[32][33];
    int tx = threadIdx.x, ty = threadIdx.y;
    int z = blockIdx.z;
    if (z < 48) {
        int sel = z >> 4, h = z & 15;
        const float* src = (sel == 0 ? wq : (sel == 1 ? wk : wv)) + (size_t)h * DD * DHH;
        int d0 = blockIdx.x * 32, dh0 = blockIdx.y * 32;   // dh0 in {0,32}
        if (blockIdx.y >= 2) return;
        #pragma unroll
        for (int j = 0; j < 4; j++)
            t[ty + j * 8][tx] = src[(size_t)(d0 + ty + j * 8) * DHH + dh0 + tx];
        __syncthreads();
        int nb = sel * DD + h * DHH + dh0;
        #pragma unroll
        for (int j = 0; j < 4; j++) {
            size_t o = (size_t)(nb + ty + j * 8) * DD + d0 + tx;
            thq[o] = __float2half_rn(t[tx][ty + j * 8]);
        }
    } else {
        int zz = z - 48;
        int sel = zz >> 5;                 // 0..2
        int c0 = (zz & 31) * 32;           // column tile
        const float* src = sel == 0 ? w0 : (sel == 1 ? w1 : w2);
        __half* dh = sel == 0 ? t0h : (sel == 1 ? t1h : t2h);
        int r0 = blockIdx.x * 32;
        if (blockIdx.y != 0) return;
        #pragma unroll
        for (int j = 0; j < 4; j++)
            t[ty + j * 8][tx] = src[(size_t)(r0 + ty + j * 8) * DD + c0 + tx];
        __syncthreads();
        #pragma unroll
        for (int j = 0; j < 4; j++) {
            size_t o = (size_t)(c0 + ty + j * 8) * DD + r0 + tx;
            dh[o] = __float2half_rn(t[tx][ty + j * 8]);
        }
    }
}

// ---------------- mma.sync fp16 GEMM: CTA 64x256, warp tile 64x64, BK=64 ----------------
#define GLDA 72
#define ATILE (64 * GLDA * 2)     // 9216
#define BTILE (256 * GLDA * 2)    // 36864
#define GSTG  (ATILE + BTILE)     // 46080
#define GSM   (2 * GSTG)          // 92160

__device__ __forceinline__ void g_load(uint32_t st,
    const __half* __restrict__ A, const __half* __restrict__ B,
    int brow, int bcol, int k0, int K, int tid)
{
    #pragma unroll
    for (int it = 0; it < 4; it++) {
        int g = tid + it * 128;
        int r = g >> 3, gi = g & 7;
        uint32_t so = (uint32_t)(r * GLDA + gi * 8) * 2;
        cpa16(st + so, A + (size_t)(brow + r) * K + k0 + gi * 8);
    }
    #pragma unroll
    for (int it = 0; it < 16; it++) {
        int g = tid + it * 128;
        int r = g >> 3, gi = g & 7;
        uint32_t so = (uint32_t)(r * GLDA + gi * 8) * 2;
        cpa16(st + ATILE + so, B + (size_t)(bcol + r) * K + k0 + gi * 8);
    }
}

template <int ADD, int RELU, int HOUT>
__global__ void __launch_bounds__(128, 2)
gemm_mma_kernel(const __half* __restrict__ A, const __half* __restrict__ B,
                float* __restrict__ Cf, __half* __restrict__ Ch,
                const float* __restrict__ R, int N, int K) {
    extern __shared__ char smg[];
    uint32_t sbase = smem_u32(smg);
    int tid = threadIdx.x, lane = tid & 31, wid = tid >> 5;
    int wn = wid * 64;
    int brow = blockIdx.y * 64, bcol = blockIdx.x * 256;
    int NC = K >> 6;

    float acc[4][8][4];
    #pragma unroll
    for (int i = 0; i < 4; i++)
        #pragma unroll
        for (int j = 0; j < 8; j++)
            #pragma unroll
            for (int e = 0; e < 4; e++) acc[i][j][e] = 0.f;

    g_load(sbase, A, B, brow, bcol, 0, K, tid); cpcommit();

    int aRow = lane & 15, aCol8 = (lane >> 4) * 8;
    int bnRow = (lane & 7) + ((lane >> 4) & 1) * 8;
    int bkCol = ((lane >> 3) & 1) * 8;

    uint32_t af[2][4][4];

    for (int c = 0; c < NC; c++) {
        cpwait<0>();
        __syncthreads();
        if (c + 1 < NC) {
            g_load(sbase + ((c + 1) & 1) * GSTG, A, B, brow, bcol, (c + 1) * 64, K, tid);
            cpcommit();
        }
        uint32_t sA = sbase + (c & 1) * GSTG;

        #pragma unroll
        for (int mt = 0; mt < 4; mt++) {
            uint32_t off = (uint32_t)((mt * 16 + aRow) * GLDA + aCol8) * 2;
            ldsm_x4(af[0][mt], sA + off);
        }

        #pragma unroll
        for (int ks = 0; ks < 4; ks++) {
            uint32_t bb[8][2];
            #pragma unroll
            for (int ntp = 0; ntp < 4; ntp++) {
                uint32_t off = (uint32_t)((wn + ntp * 16 + bnRow) * GLDA + ks * 16 + bkCol) * 2;
                ldsm_x4(&bb[ntp * 2][0], sA + ATILE + off);
            }
            if (ks < 3) {
                #pragma unroll
                for (int mt = 0; mt < 4; mt++) {
                    uint32_t off = (uint32_t)((mt * 16 + aRow) * GLDA + (ks + 1) * 16 + aCol8) * 2;
                    ldsm_x4(af[(ks + 1) & 1][mt], sA + off);
                }
            }
            #pragma unroll
            for (int mt = 0; mt < 4; mt++)
                #pragma unroll
                for (int nt = 0; nt < 8; nt++)
                    mma16816(acc[mt][nt], af[ks & 1][mt], bb[nt]);
        }
    }

    int r0 = brow + (lane >> 2);
    int c0 = bcol + wn + (lane & 3) * 2;
    #pragma unroll
    for (int mt = 0; mt < 4; mt++)
        #pragma unroll
        for (int half = 0; half < 2; half++) {
            int row = r0 + mt * 16 + half * 8;
            #pragma unroll
            for (int nt = 0; nt < 8; nt++) {
                float vx = acc[mt][nt][half * 2], vy = acc[mt][nt][half * 2 + 1];
                size_t o = (size_t)row * N + c0 + nt * 8;
                if (ADD) { vx += R[o]; vy += R[o + 1]; }
                if (RELU) { vx = fmaxf(vx, 0.f); vy = fmaxf(vy, 0.f); }
                if (HOUT) {
                    *(uint32_t*)&Ch[o] = packh(vx, vy);
                } else {
                    *(float2*)&Cf[o] = make_float2(vx, vy);
                }
            }
        }
}

// ---------------- flash attention (64q, 128 threads, occ 4) ----------------
#define FST 72
#define F_Q 0
#define F_ST0 9216
#define F_STG 18432
#define F_SM (F_ST0 + 2 * F_STG)   // 46080

__device__ __forceinline__ void f_load_tile(uint32_t st,
    const __half* __restrict__ qkv, int b, int h, int krow, int tid)
{
    #pragma unroll
    for (int i = 0; i < 4; i++) {
        int g = tid + i * 128, r = g >> 3, gr = g & 7;
        size_t kro = (size_t)(b * SS + krow + r) * LD3 + DD + h * DHH + gr * 8;
        uint32_t dst = (uint32_t)(r * FST + gr * 8) * 2;
        cpa16(st + dst,        qkv + kro);
        cpa16(st + 9216 + dst, qkv + kro + DD);
    }
}

__global__ void __launch_bounds__(128, 4)
flash_mma_kernel(const __half* __restrict__ qkv, __half* __restrict__ ch) {
    extern __shared__ char smf[];
    uint32_t sb = smem_u32(smf);
    int tid = threadIdx.x, lane = tid & 31, w = tid >> 5;
    int b = blockIdx.z, h = blockIdx.y, q0 = blockIdx.x * 64;

    #pragma unroll
    for (int i = 0; i < 4; i++) {
        int g = tid + i * 128, r = g >> 3, gr = g & 7;
        size_t src = (size_t)(b * SS + q0 + r) * LD3 + h * DHH + gr * 8;
        uint32_t dst = (uint32_t)(r * FST + gr * 8) * 2;
        cpa16(sb + F_Q + dst, qkv + src);
    }
    cpcommit();
    f_load_tile(sb + F_ST0, qkv, b, h, 0, tid);
    cpcommit();

    cpwait<1>();
    __syncthreads();
    int lr = lane & 15, hc = (lane >> 4) * 8;
    uint32_t Qf[4][4];
    #pragma unroll
    for (int kk = 0; kk < 4; kk++) {
        uint32_t off = (uint32_t)((16 * w + lr) * FST + kk * 16 + hc) * 2;
        ldsm_x4(Qf[kk], sb + F_Q + off);
    }

    int bnRow = (lane & 7) + ((lane >> 4) & 1) * 8;
    int bkCol = ((lane >> 3) & 1) * 8;
    int vRow = (lane & 7) + ((lane >> 3) & 1) * 8;
    int vCol = (lane >> 4) * 8;

    float m0 = -1e30f, m1 = -1e30f, l0 = 0.f, l1 = 0.f;
    float ao[8][4];
    #pragma unroll
    for (int n = 0; n < 8; n++)
        #pragma unroll
        for (int e = 0; e < 4; e++) ao[n][e] = 0.f;

    for (int kb = 0; kb < SS; kb += 64) {
        int t = kb >> 6;
        cpwait<0>();
        __syncthreads();
        if (kb + 64 < SS) {
            f_load_tile(sb + F_ST0 + ((t + 1) & 1) * F_STG, qkv, b, h, kb + 64, tid);
            cpcommit();
        }
        uint32_t st = sb + F_ST0 + (t & 1) * F_STG;

        float s_[8][4];
        #pragma unroll
        for (int n = 0; n < 8; n++)
            #pragma unroll
            for (int e = 0; e < 4; e++) s_[n][e] = 0.f;
        #pragma unroll
        for (int kk = 0; kk < 4; kk++) {
            uint32_t bh[8][2];
            #pragma unroll
            for (int ntp = 0; ntp < 4; ntp++) {
                uint32_t off = (uint32_t)((ntp * 16 + bnRow) * FST + kk * 16 + bkCol) * 2;
                ldsm_x4(&bh[ntp * 2][0], st + off);
            }
            #pragma unroll
            for (int nt = 0; nt < 8; nt++) mma16816(s_[nt], Qf[kk], bh[nt]);
        }

        float tm0 = -1e30f, tm1 = -1e30f;
        #pragma unroll
        for (int n = 0; n < 8; n++) {
            #pragma unroll
            for (int e = 0; e < 4; e++) s_[n][e] *= 0.125f;
            tm0 = fmaxf(tm0, fmaxf(s_[n][0], s_[n][1]));
            tm1 = fmaxf(tm1, fmaxf(s_[n][2], s_[n][3]));
        }
        tm0 = fmaxf(tm0, __shfl_xor_sync(0xffffffffu, tm0, 1));
        tm0 = fmaxf(tm0, __shfl_xor_sync(0xffffffffu, tm0, 2));
        tm1 = fmaxf(tm1, __shfl_xor_sync(0xffffffffu, tm1, 1));
        tm1 = fmaxf(tm1, __shfl_xor_sync(0xffffffffu, tm1, 2));
        float mn0 = fmaxf(m0, tm0), mn1 = fmaxf(m1, tm1);
        float sc0 = __expf(m0 - mn0), sc1 = __expf(m1 - mn1);
        m0 = mn0; m1 = mn1;
        float ls0 = 0.f, ls1 = 0.f;
        #pragma unroll
        for (int n = 0; n < 8; n++) {
            s_[n][0] = __expf(s_[n][0] - mn0);
            s_[n][1] = __expf(s_[n][1] - mn0);
            s_[n][2] = __expf(s_[n][2] - mn1);
            s_[n][3] = __expf(s_[n][3] - mn1);
            ls0 += s_[n][0] + s_[n][1];
            ls1 += s_[n][2] + s_[n][3];
        }
        ls0 += __shfl_xor_sync(0xffffffffu, ls0, 1);
        ls0 += __shfl_xor_sync(0xffffffffu, ls0, 2);
        ls1 += __shfl_xor_sync(0xffffffffu, ls1, 1);
        ls1 += __shfl_xor_sync(0xffffffffu, ls1, 2);
        l0 = l0 * sc0 + ls0;
        l1 = l1 * sc1 + ls1;
        #pragma unroll
        for (int n = 0; n < 8; n++) {
            ao[n][0] *= sc0; ao[n][1] *= sc0;
            ao[n][2] *= sc1; ao[n][3] *= sc1;
        }

        #pragma unroll
        for (int k2 = 0; k2 < 4; k2++) {
            uint32_t pa[4];
            pa[0] = packh(s_[2 * k2][0],     s_[2 * k2][1]);
            pa[1] = packh(s_[2 * k2][2],     s_[2 * k2][3]);
            pa[2] = packh(s_[2 * k2 + 1][0], s_[2 * k2 + 1][1]);
            pa[3] = packh(s_[2 * k2 + 1][2], s_[2 * k2 + 1][3]);
            #pragma unroll
            for (int ntp = 0; ntp < 4; ntp++) {
                uint32_t bv[4];
                ldsm_x4t(bv, st + 9216
                         + (uint32_t)((k2 * 16 + vRow) * FST + ntp * 16 + vCol) * 2);
                mma16816(ao[ntp * 2],     pa, &bv[0]);
                mma16816(ao[ntp * 2 + 1], pa, &bv[2]);
            }
        }
    }

    float i0 = 1.0f / l0, i1 = 1.0f / l1;
    int row0 = b * SS + q0 + 16 * w + (lane >> 2);
    int cb = h * DHH + (lane & 3) * 2;
    #pragma unroll
    for (int nt = 0; nt < 8; nt++) {
        size_t o0 = (size_t)row0 * DD + cb + nt * 8;
        size_t o1 = (size_t)(row0 + 8) * DD + cb + nt * 8;
        *(uint32_t*)&ch[o0] = packh(ao[nt][0] * i0, ao[nt][1] * i0);
        *(uint32_t*)&ch[o1] = packh(ao[nt][2] * i1, ao[nt][3] * i1);
    }
}

// ---------------- launch ----------------
#define SYM(p, s) cudaGetSymbolAddress((void**)&p, s)

extern "C" void kernel_launch(void* const* d_in, const int* in_sizes, int n_in,
                              void* d_out, int out_size) {
    const float* x     = (const float*)d_in[0];
    const float* wq    = (const float*)d_in[1];
    const float* wk    = (const float*)d_in[2];
    const float* wv    = (const float*)d_in[3];
    const float* wo    = (const float*)d_in[4];
    const float* w1    = (const float*)d_in[5];
    const float* w2    = (const float*)d_in[6];
    const float* ln1_g = (const float*)d_in[7];
    const float* ln1_b = (const float*)d_in[8];
    const float* ln2_g = (const float*)d_in[9];
    const float* ln2_b = (const float*)d_in[10];
    const float* ln3_g = (const float*)d_in[11];
    const float* ln3_b = (const float*)d_in[12];
    float* out = (float*)d_out;

    float *p_attn, *p_ln2f, *p_res2;
    __half *p_ln1h, *p_ln2h, *p_ctxh, *p_f1h, *p_qkvh;
    __half *p_wqh, *p_woh, *p_w1h, *p_w2h;
    SYM(p_attn, g_attn); SYM(p_ln2f, g_ln2f); SYM(p_res2, g_res2);
    SYM(p_ln1h, g_ln1h); SYM(p_ln2h, g_ln2h);
    SYM(p_ctxh, g_ctxh); SYM(p_f1h, g_f1h); SYM(p_qkvh, g_qkvh);
    SYM(p_wqh, g_wqh); SYM(p_woh, g_woh); SYM(p_w1h, g_w1h); SYM(p_w2h, g_w2h);

    cudaFuncSetAttribute(gemm_mma_kernel<0,0,1>, cudaFuncAttributeMaxDynamicSharedMemorySize, GSM);
    cudaFuncSetAttribute(gemm_mma_kernel<1,0,0>, cudaFuncAttributeMaxDynamicSharedMemorySize, GSM);
    cudaFuncSetAttribute(gemm_mma_kernel<0,1,1>, cudaFuncAttributeMaxDynamicSharedMemorySize, GSM);
    cudaFuncSetAttribute(flash_mma_kernel, cudaFuncAttributeMaxDynamicSharedMemorySize, F_SM);

    // fused weight prep: z<48 -> qkv tiles (needs blockIdx.y<2); z>=48 -> square tiles (y=0)
    transpose_all_kernel<<<dim3(DD / 32, 2, 144), dim3(32, 8)>>>(
        wq, wk, wv, wo, w1, w2, p_wqh, p_woh, p_w1h, p_w2h);

    layernorm_kernel<<<MM, 256>>>(x, ln1_g, ln1_b, nullptr, p_ln1h);
    gemm_mma_kernel<0,0,1><<<dim3(LD3 / 256, MM / 64), 128, GSM>>>(
        p_ln1h, p_wqh, nullptr, p_qkvh, nullptr, LD3, DD);
    flash_mma_kernel<<<dim3(SS / 64, HH, BB), 128, F_SM>>>(p_qkvh, p_ctxh);
    gemm_mma_kernel<1,0,0><<<dim3(DD / 256, MM / 64), 128, GSM>>>(
        p_ctxh, p_woh, p_attn, nullptr, x, DD, DD);
    layernorm_kernel<<<MM, 256>>>(p_attn, ln2_g, ln2_b, p_ln2f, p_ln2h);
    gemm_mma_kernel<0,1,1><<<dim3(DD / 256, MM / 64), 128, GSM>>>(
        p_ln2h, p_w1h, nullptr, p_f1h, nullptr, DD, DD);
    gemm_mma_kernel<1,0,0><<<dim3(DD / 256, MM / 64), 128, GSM>>>(
        p_f1h, p_w2h, p_res2, nullptr, p_ln2f, DD, DD);
    layernorm_kernel<<<MM, 256>>>(p_res2, ln3_g, ln3_b, out, nullptr);
}